// round 8
// baseline (speedup 1.0000x reference)
#include <cuda_runtime.h>
#include <cuda_fp16.h>
#include <math.h>
#include <stdint.h>

#define SS 2048
#define NN 32
#define HH 1024
#define EE 1024
#define MM (SS*NN)   // 65536 rows

// ---- scratch (static __device__: no allocation in kernel_launch) ----
__device__ float  g_u[NN*EE];
__device__ float  g_a[NN*SS];
__device__ float  g_alpha[NN*SS];
__device__ float  g_cpart[32*NN*HH];
__device__ __half g_Xh[(size_t)MM*HH];   // fp16 copy of out_e (128MB)
__device__ __half g_W2h[(size_t)EE*HH];  // fp16 copy of W2 (2MB)

// ============================================================================
// PTX helpers (sm_80+ portable)
// ============================================================================
__device__ __forceinline__ uint32_t smem_u32(const void* p) {
    uint32_t a;
    asm("{ .reg .u64 t; cvta.to.shared.u64 t, %1; cvt.u32.u64 %0, t; }" : "=r"(a) : "l"(p));
    return a;
}
#define CP_ASYNC16(dst, src) \
    asm volatile("cp.async.cg.shared.global [%0], [%1], 16;" :: "r"(dst), "l"(src) : "memory")
#define CP_COMMIT() asm volatile("cp.async.commit_group;" ::: "memory")
#define CP_WAIT1()  asm volatile("cp.async.wait_group 1;" ::: "memory")
#define CP_WAIT0()  asm volatile("cp.async.wait_group 0;" ::: "memory")

#define LDSM_X4(r0, r1, r2, r3, addr) \
    asm volatile("ldmatrix.sync.aligned.m8n8.x4.shared.b16 {%0,%1,%2,%3}, [%4];" \
        : "=r"(r0), "=r"(r1), "=r"(r2), "=r"(r3) : "r"(addr))

__device__ __forceinline__ void mma_f16(float c[4],
                                        uint32_t a0, uint32_t a1, uint32_t a2, uint32_t a3,
                                        uint32_t b0, uint32_t b1) {
    asm volatile(
        "mma.sync.aligned.m16n8k16.row.col.f32.f16.f16.f32 "
        "{%0,%1,%2,%3}, {%4,%5,%6,%7}, {%8,%9}, {%0,%1,%2,%3};"
        : "+f"(c[0]), "+f"(c[1]), "+f"(c[2]), "+f"(c[3])
        : "r"(a0), "r"(a1), "r"(a2), "r"(a3), "r"(b0), "r"(b1));
}

// ============================================================================
// Kernel 0: fp32 -> fp16 conversion
// ============================================================================
__global__ void k_cvt(const float* __restrict__ src, __half* __restrict__ dst, int n4) {
    int i = blockIdx.x * blockDim.x + threadIdx.x;
    if (i >= n4) return;
    float4 v = ((const float4*)src)[i];
    __half2 lo = __floats2half2_rn(v.x, v.y);
    __half2 hi = __floats2half2_rn(v.z, v.w);
    uint2 w;
    w.x = *(uint32_t*)&lo;
    w.y = *(uint32_t*)&hi;
    ((uint2*)dst)[i] = w;
}

// ============================================================================
// Kernel 1: u[n][e] = hidden_d[n]·W1[e] + b1[e] + b2[e]
// ============================================================================
__global__ void k_u(const float* __restrict__ hidden, const float* __restrict__ W1,
                    const float* __restrict__ b1, const float* __restrict__ b2) {
    int gw = (blockIdx.x * blockDim.x + threadIdx.x) >> 5;
    int lane = threadIdx.x & 31;
    if (gw >= NN * EE) return;
    int n = gw >> 10;
    int e = gw & (EE - 1);
    const float* hv = hidden + n * HH;
    const float* wv = W1 + (size_t)e * HH;
    float s = 0.f;
    #pragma unroll 4
    for (int h = lane; h < HH; h += 32) s = fmaf(hv[h], wv[h], s);
    #pragma unroll
    for (int o = 16; o; o >>= 1) s += __shfl_down_sync(0xffffffffu, s, o);
    if (lane == 0) g_u[n * EE + e] = s + b1[e] + b2[e];
}

// ============================================================================
// Kernel 2: fp16 mma.sync fused  X·W2ᵀ -> +u -> tanh -> ·W3 reduce -> a[m]
//   Block: 128 rows x 256 e-cols per n-tile (4 n-tiles for E=1024).
//   8 warps, warp tile 64x64 (2m x 4n). K-chunks of 64 halfs, 3 smem buffers.
//   Fragments double-buffered across the 4 k16-steps to hide LDSM latency.
// ============================================================================
#define NSTG 64           // 4 n-tiles * 16 k-chunks
#define AST 72            // smem stride (halfs)
#define A_TILE_B (128*AST*2)   // 18432 B
#define B_TILE_B (256*AST*2)   // 36864 B
#define NTILE 256
#define SU_STRIDE 264     // 256 + 8 pad (floats)

__global__ void __launch_bounds__(256, 1)
k_gemm(const float* __restrict__ W3, const float* __restrict__ b3) {
    extern __shared__ char smraw[];
    __half* As = (__half*)smraw;                                  // 3 * 18432 B
    __half* Bs = (__half*)(smraw + 3 * A_TILE_B);                 // 3 * 36864 B
    float*  su = (float*)(smraw + 3 * A_TILE_B + 3 * B_TILE_B);   // 32*264*4 B
    float* red = su + 32 * SU_STRIDE;                             // 128*4 floats

    const int tid = threadIdx.x;
    const int wid = tid >> 5;
    const int lid = tid & 31;
    const int g   = lid >> 2;
    const int tg  = lid & 3;
    const int warp_m = wid & 1;        // 2 m-warps of 64 rows
    const int warp_n = wid >> 1;       // 4 n-warps of 64 cols
    const int mbase = warp_m * 64;
    const int nbase = warp_n * 64;
    const int m0 = blockIdx.x * 128;

    const uint32_t sA = smem_u32(As);
    const uint32_t sB = smem_u32(Bs);

    const int l_ch  = tid & 7;         // 16B chunk within 128B row
    const int l_row = tid >> 3;        // 0..31

    const __half* Xh  = g_Xh;
    const __half* W2h = g_W2h;

    auto do_load = [&](int ls) {
        int nt  = ls >> 4;
        int kc  = ls & 15;
        int buf = ls - (ls / 3) * 3;
        const __half* gA = Xh  + (size_t)(m0 + l_row) * HH + kc * 64 + l_ch * 8;
        uint32_t dA = sA + buf * A_TILE_B + l_row * (AST * 2) + l_ch * 16;
        #pragma unroll
        for (int t = 0; t < 4; t++) {
            CP_ASYNC16(dA, gA);
            gA += 32 * HH;
            dA += 32 * AST * 2;
        }
        const __half* gB = W2h + (size_t)(nt * NTILE + l_row) * HH + kc * 64 + l_ch * 8;
        uint32_t dB = sB + buf * B_TILE_B + l_row * (AST * 2) + l_ch * 16;
        #pragma unroll
        for (int t = 0; t < 8; t++) {
            CP_ASYNC16(dB, gB);
            gB += 32 * HH;
            dB += 32 * AST * 2;
        }
        CP_COMMIT();
    };

    float acc[4][8][4];
    #pragma unroll
    for (int i = 0; i < 4; i++)
        #pragma unroll
        for (int j = 0; j < 8; j++)
            #pragma unroll
            for (int q = 0; q < 4; q++) acc[i][j][q] = 0.f;
    float pa[8];
    #pragma unroll
    for (int i = 0; i < 8; i++) pa[i] = 0.f;

    // ldmatrix lane-address components
    const int a_row_l  = ((lid >> 3) & 1) * 8 + (lid & 7);
    const int a_koff_l = (lid >> 4) * 8;
    const int b_row_l  = ((lid >> 4) & 1) * 8 + (lid & 7);
    const int b_koff_l = ((lid >> 3) & 1) * 8;

    do_load(0);
    do_load(1);

    for (int ls = 0; ls < NSTG; ++ls) {
        int kc  = ls & 15;
        int nt  = ls >> 4;
        int buf = ls - (ls / 3) * 3;

        if (ls < NSTG - 1) { CP_WAIT1(); } else { CP_WAIT0(); }
        __syncthreads();

        const uint32_t Ab = sA + buf * A_TILE_B;
        const uint32_t Bb = sB + buf * B_TILE_B;

        // fragment double buffers across k16-steps
        uint32_t af[2][4][4], bf[2][4][4];

        // prologue: load fragments for q=0
        #pragma unroll
        for (int i = 0; i < 4; i++) {
            uint32_t addr = Ab + (mbase + i * 16 + a_row_l) * (AST * 2) + a_koff_l * 2;
            LDSM_X4(af[0][i][0], af[0][i][1], af[0][i][2], af[0][i][3], addr);
        }
        #pragma unroll
        for (int j2 = 0; j2 < 4; j2++) {
            uint32_t addr = Bb + (nbase + j2 * 16 + b_row_l) * (AST * 2) + b_koff_l * 2;
            LDSM_X4(bf[0][j2][0], bf[0][j2][1], bf[0][j2][2], bf[0][j2][3], addr);
        }

        #pragma unroll
        for (int q = 0; q < 4; q++) {
            const int cur = q & 1;
            const int nxt = cur ^ 1;
            if (q < 3) {
                // prefetch next k16-step fragments; overlaps with this step's MMAs
                #pragma unroll
                for (int i = 0; i < 4; i++) {
                    uint32_t addr = Ab + (mbase + i * 16 + a_row_l) * (AST * 2)
                                  + ((q + 1) * 16 + a_koff_l) * 2;
                    LDSM_X4(af[nxt][i][0], af[nxt][i][1], af[nxt][i][2], af[nxt][i][3], addr);
                }
                #pragma unroll
                for (int j2 = 0; j2 < 4; j2++) {
                    uint32_t addr = Bb + (nbase + j2 * 16 + b_row_l) * (AST * 2)
                                  + ((q + 1) * 16 + b_koff_l) * 2;
                    LDSM_X4(bf[nxt][j2][0], bf[nxt][j2][1], bf[nxt][j2][2], bf[nxt][j2][3], addr);
                }
            }
            #pragma unroll
            for (int j2 = 0; j2 < 4; j2++) {
                #pragma unroll
                for (int i = 0; i < 4; i++) {
                    mma_f16(acc[i][j2 * 2],     af[cur][i][0], af[cur][i][1],
                            af[cur][i][2], af[cur][i][3], bf[cur][j2][0], bf[cur][j2][1]);
                    mma_f16(acc[i][j2 * 2 + 1], af[cur][i][0], af[cur][i][1],
                            af[cur][i][2], af[cur][i][3], bf[cur][j2][2], bf[cur][j2][3]);
                }
            }
        }

        if (kc == 0) {
            // stage u[0..31][nt*256 .. +255] into smem (readers at kc==15)
            #pragma unroll
            for (int t = 0; t < 32; t++) {
                int idx = tid + t * 256;
                int n = idx >> 8, el = idx & 255;
                su[n * SU_STRIDE + el] = g_u[n * EE + nt * NTILE + el];
            }
        }

        if (kc == 15) {
            // epilogue: +u, tanh, *W3; fold into row partials; reset acc
            #pragma unroll
            for (int i = 0; i < 4; i++) {
                int r0 = mbase + i * 16 + g;
                int n0 = r0 & 31;
                int n1 = (r0 + 8) & 31;
                #pragma unroll
                for (int j = 0; j < 8; j++) {
                    int el = nbase + j * 8 + 2 * tg;
                    int e  = nt * NTILE + el;
                    float w30 = __ldg(&W3[e]);
                    float w31 = __ldg(&W3[e + 1]);
                    float z00 = acc[i][j][0] + su[n0 * SU_STRIDE + el];
                    float z01 = acc[i][j][1] + su[n0 * SU_STRIDE + el + 1];
                    float z10 = acc[i][j][2] + su[n1 * SU_STRIDE + el];
                    float z11 = acc[i][j][3] + su[n1 * SU_STRIDE + el + 1];
                    pa[i * 2]     = fmaf(tanhf(z00), w30, pa[i * 2]);
                    pa[i * 2]     = fmaf(tanhf(z01), w31, pa[i * 2]);
                    pa[i * 2 + 1] = fmaf(tanhf(z10), w30, pa[i * 2 + 1]);
                    pa[i * 2 + 1] = fmaf(tanhf(z11), w31, pa[i * 2 + 1]);
                    acc[i][j][0] = acc[i][j][1] = acc[i][j][2] = acc[i][j][3] = 0.f;
                }
            }
        }

        __syncthreads();
        if (ls + 2 < NSTG) do_load(ls + 2);
    }

    // reduce pa over 4 lanes of each group, then across the 4 n-warps
    #pragma unroll
    for (int i = 0; i < 4; i++)
        #pragma unroll
        for (int h = 0; h < 2; h++) {
            float v = pa[i * 2 + h];
            v += __shfl_xor_sync(0xffffffffu, v, 1);
            v += __shfl_xor_sync(0xffffffffu, v, 2);
            if (tg == 0) red[(mbase + i * 16 + h * 8 + g) * 4 + warp_n] = v;
        }
    __syncthreads();
    if (tid < 128) {
        int m = m0 + tid;
        float a = red[tid * 4] + red[tid * 4 + 1] + red[tid * 4 + 2] + red[tid * 4 + 3]
                + __ldg(&b3[0]);
        g_a[(m & 31) * SS + (m >> 5)] = a;
    }
}

// ============================================================================
// Kernel 3: softmax over S per column n
// ============================================================================
__global__ void k_softmax(float* __restrict__ alpha_out, int write_out) {
    int n = blockIdx.x;
    int tid = threadIdx.x;
    __shared__ float sred[256];
    const float* av = g_a + n * SS;

    float vals[8];
    float mx = -1e30f;
    #pragma unroll
    for (int i = 0; i < 8; i++) { vals[i] = av[tid + i * 256]; mx = fmaxf(mx, vals[i]); }
    sred[tid] = mx; __syncthreads();
    for (int o = 128; o; o >>= 1) { if (tid < o) sred[tid] = fmaxf(sred[tid], sred[tid + o]); __syncthreads(); }
    mx = sred[0]; __syncthreads();

    float lsum = 0.f;
    #pragma unroll
    for (int i = 0; i < 8; i++) { vals[i] = __expf(vals[i] - mx); lsum += vals[i]; }
    sred[tid] = lsum; __syncthreads();
    for (int o = 128; o; o >>= 1) { if (tid < o) sred[tid] += sred[tid + o]; __syncthreads(); }
    float inv = 1.f / sred[0];

    #pragma unroll
    for (int i = 0; i < 8; i++) {
        int s = tid + i * 256;
        float al = vals[i] * inv;
        g_alpha[n * SS + s] = al;
        if (write_out) alpha_out[s * NN + n] = al;
    }
}

// ============================================================================
// Kernel 4/5: context c[n][h] = sum_s alpha[s,n]*x[s,n,h]  (fp16 x, fp32 acc)
// ============================================================================
__global__ void k_cpart() {
    int chunk = blockIdx.x;   // 0..31
    int n     = blockIdx.y;   // 0..31
    int h0    = threadIdx.x * 4;
    float4 acc = make_float4(0.f, 0.f, 0.f, 0.f);
    int sbeg = chunk * (SS / 32);
    for (int s = sbeg; s < sbeg + (SS / 32); ++s) {
        float al = g_alpha[n * SS + s];
        uint2 raw = *(const uint2*)(g_Xh + (size_t)(s * NN + n) * HH + h0);
        __half2 hlo = *(__half2*)&raw.x;
        __half2 hhi = *(__half2*)&raw.y;
        float2 lo = __half22float2(hlo);
        float2 hi = __half22float2(hhi);
        acc.x = fmaf(al, lo.x, acc.x);
        acc.y = fmaf(al, lo.y, acc.y);
        acc.z = fmaf(al, hi.x, acc.z);
        acc.w = fmaf(al, hi.y, acc.w);
    }
    *(float4*)(g_cpart + ((size_t)(chunk * NN + n) * HH) + h0) = acc;
}

__global__ void k_cfinal(float* __restrict__ cout) {
    int idx = blockIdx.x * 256 + threadIdx.x;   // 0 .. N*H-1
    float s = 0.f;
    #pragma unroll
    for (int ch = 0; ch < 32; ++ch) s += g_cpart[(size_t)ch * NN * HH + idx];
    cout[idx] = s;
}

// ============================================================================
extern "C" void kernel_launch(void* const* d_in, const int* in_sizes, int n_in,
                              void* d_out, int out_size) {
    const float* out_e  = (const float*)d_in[0];
    const float* hidden = (const float*)d_in[1];
    const float* W1     = (const float*)d_in[2];
    const float* b1     = (const float*)d_in[3];
    const float* W2     = (const float*)d_in[4];
    const float* b2     = (const float*)d_in[5];
    const float* W3     = (const float*)d_in[6];
    const float* b3     = (const float*)d_in[7];
    float* outp = (float*)d_out;

    __half *dXh = nullptr, *dW2h = nullptr;
    cudaGetSymbolAddress((void**)&dXh,  g_Xh);
    cudaGetSymbolAddress((void**)&dW2h, g_W2h);
    k_cvt<<<((size_t)MM * HH / 4 + 255) / 256, 256>>>(out_e, dXh, MM * (HH / 4));
    k_cvt<<<(EE * HH / 4 + 255) / 256, 256>>>(W2, dW2h, EE * HH / 4);

    k_u<<<(NN * EE) / 8, 256>>>(hidden, W1, b1, b2);

    const int smem_bytes = 3 * A_TILE_B + 3 * B_TILE_B + (32 * SU_STRIDE + 128 * 4) * 4;
    static int cfg_done = 0;
    if (!cfg_done) {
        cudaFuncSetAttribute(k_gemm, cudaFuncAttributeMaxDynamicSharedMemorySize, smem_bytes);
        cfg_done = 1;
    }
    k_gemm<<<MM / 128, 256, smem_bytes>>>(W3, b3);

    int has_both   = (out_size >= NN * HH + SS * NN);
    int alpha_only = (!has_both && out_size == SS * NN);
    float* alpha_dst = has_both ? (outp + NN * HH) : (alpha_only ? outp : nullptr);

    k_softmax<<<NN, 256>>>(alpha_dst, alpha_dst != nullptr);

    if (!alpha_only) {
        dim3 g(32, NN);
        k_cpart<<<g, 256>>>();
        k_cfinal<<<(NN * HH) / 256, 256>>>(outp);
    }
}

// round 11
// speedup vs baseline: 1.0029x; 1.0029x over previous
#include <cuda_runtime.h>
#include <cuda_fp16.h>
#include <math.h>
#include <stdint.h>

#define SS 2048
#define NN 32
#define HH 1024
#define EE 1024
#define MM (SS*NN)   // 65536 rows

// ---- scratch (static __device__: no allocation in kernel_launch) ----
__device__ float  g_u[NN*EE];
__device__ float  g_a[NN*SS];
__device__ float  g_alpha[NN*SS];
__device__ float  g_cpart[32*NN*HH];
__device__ __half g_Xh[(size_t)MM*HH];   // fp16 copy of out_e (128MB)
__device__ __half g_W2h[(size_t)EE*HH];  // fp16 copy of W2 (2MB)

// ============================================================================
// PTX helpers (sm_80+ portable)
// ============================================================================
__device__ __forceinline__ uint32_t smem_u32(const void* p) {
    uint32_t a;
    asm("{ .reg .u64 t; cvta.to.shared.u64 t, %1; cvt.u32.u64 %0, t; }" : "=r"(a) : "l"(p));
    return a;
}
#define CP_ASYNC16(dst, src) \
    asm volatile("cp.async.cg.shared.global [%0], [%1], 16;" :: "r"(dst), "l"(src) : "memory")
#define CP_COMMIT() asm volatile("cp.async.commit_group;" ::: "memory")
#define CP_WAIT1()  asm volatile("cp.async.wait_group 1;" ::: "memory")
#define CP_WAIT0()  asm volatile("cp.async.wait_group 0;" ::: "memory")

#define LDSM_X4(r0, r1, r2, r3, addr) \
    asm volatile("ldmatrix.sync.aligned.m8n8.x4.shared.b16 {%0,%1,%2,%3}, [%4];" \
        : "=r"(r0), "=r"(r1), "=r"(r2), "=r"(r3) : "r"(addr))

__device__ __forceinline__ void mma_f16(float c[4],
                                        uint32_t a0, uint32_t a1, uint32_t a2, uint32_t a3,
                                        uint32_t b0, uint32_t b1) {
    asm volatile(
        "mma.sync.aligned.m16n8k16.row.col.f32.f16.f16.f32 "
        "{%0,%1,%2,%3}, {%4,%5,%6,%7}, {%8,%9}, {%0,%1,%2,%3};"
        : "+f"(c[0]), "+f"(c[1]), "+f"(c[2]), "+f"(c[3])
        : "r"(a0), "r"(a1), "r"(a2), "r"(a3), "r"(b0), "r"(b1));
}

// ============================================================================
// Kernel 0: fp32 -> fp16 conversion
// ============================================================================
__global__ void k_cvt(const float* __restrict__ src, __half* __restrict__ dst, int n4) {
    int i = blockIdx.x * blockDim.x + threadIdx.x;
    if (i >= n4) return;
    float4 v = ((const float4*)src)[i];
    __half2 lo = __floats2half2_rn(v.x, v.y);
    __half2 hi = __floats2half2_rn(v.z, v.w);
    uint2 w;
    w.x = *(uint32_t*)&lo;
    w.y = *(uint32_t*)&hi;
    ((uint2*)dst)[i] = w;
}

// ============================================================================
// Kernel 1: u[n][e] = hidden_d[n]·W1[e] + b1[e] + b2[e]
// ============================================================================
__global__ void k_u(const float* __restrict__ hidden, const float* __restrict__ W1,
                    const float* __restrict__ b1, const float* __restrict__ b2) {
    int gw = (blockIdx.x * blockDim.x + threadIdx.x) >> 5;
    int lane = threadIdx.x & 31;
    if (gw >= NN * EE) return;
    int n = gw >> 10;
    int e = gw & (EE - 1);
    const float* hv = hidden + n * HH;
    const float* wv = W1 + (size_t)e * HH;
    float s = 0.f;
    #pragma unroll 4
    for (int h = lane; h < HH; h += 32) s = fmaf(hv[h], wv[h], s);
    #pragma unroll
    for (int o = 16; o; o >>= 1) s += __shfl_down_sync(0xffffffffu, s, o);
    if (lane == 0) g_u[n * EE + e] = s + b1[e] + b2[e];
}

// ============================================================================
// Kernel 2: fp16 mma.sync fused  X·W2ᵀ -> +u -> tanh -> ·W3 reduce -> a[m]
//   Block: 128 rows x 256 e-cols per n-tile (4 n-tiles for E=1024).
//   512 threads = 16 warps, warp tile 32x64 (4m x 4n) -> 4 warps/SMSP for
//   latency hiding. K-chunks of 64 halfs, 3 smem buffers.
// ============================================================================
#define NSTG 64           // 4 n-tiles * 16 k-chunks
#define AST 72            // smem stride (halfs)
#define A_TILE_B (128*AST*2)   // 18432 B
#define B_TILE_B (256*AST*2)   // 36864 B
#define NTILE 256
#define SU_STRIDE 264     // 256 + 8 pad (floats)
#define NTHR 512

__global__ void __launch_bounds__(NTHR, 1)
k_gemm(const float* __restrict__ W3, const float* __restrict__ b3) {
    extern __shared__ char smraw[];
    __half* As = (__half*)smraw;                                  // 3 * 18432 B
    __half* Bs = (__half*)(smraw + 3 * A_TILE_B);                 // 3 * 36864 B
    float*  su = (float*)(smraw + 3 * A_TILE_B + 3 * B_TILE_B);   // 32*264*4 B
    float* red = su + 32 * SU_STRIDE;                             // 128*4 floats

    const int tid = threadIdx.x;
    const int wid = tid >> 5;
    const int lid = tid & 31;
    const int g   = lid >> 2;
    const int tg  = lid & 3;
    const int warp_m = wid & 3;        // 4 m-warps of 32 rows
    const int warp_n = wid >> 2;       // 4 n-warps of 64 cols
    const int mbase = warp_m * 32;
    const int nbase = warp_n * 64;
    const int m0 = blockIdx.x * 128;

    const uint32_t sA = smem_u32(As);
    const uint32_t sB = smem_u32(Bs);

    const int l_ch  = tid & 7;         // 16B chunk within 128B row
    const int l_row = tid >> 3;        // 0..63

    const __half* Xh  = g_Xh;
    const __half* W2h = g_W2h;

    auto do_load = [&](int ls) {
        int nt  = ls >> 4;
        int kc  = ls & 15;
        int buf = ls - (ls / 3) * 3;
        const __half* gA = Xh  + (size_t)(m0 + l_row) * HH + kc * 64 + l_ch * 8;
        uint32_t dA = sA + buf * A_TILE_B + l_row * (AST * 2) + l_ch * 16;
        #pragma unroll
        for (int t = 0; t < 2; t++) {
            CP_ASYNC16(dA, gA);
            gA += 64 * HH;
            dA += 64 * AST * 2;
        }
        const __half* gB = W2h + (size_t)(nt * NTILE + l_row) * HH + kc * 64 + l_ch * 8;
        uint32_t dB = sB + buf * B_TILE_B + l_row * (AST * 2) + l_ch * 16;
        #pragma unroll
        for (int t = 0; t < 4; t++) {
            CP_ASYNC16(dB, gB);
            gB += 64 * HH;
            dB += 64 * AST * 2;
        }
        CP_COMMIT();
    };

    float acc[2][8][4];
    #pragma unroll
    for (int i = 0; i < 2; i++)
        #pragma unroll
        for (int j = 0; j < 8; j++)
            #pragma unroll
            for (int q = 0; q < 4; q++) acc[i][j][q] = 0.f;
    float pa[4] = {0.f, 0.f, 0.f, 0.f};

    // ldmatrix lane-address components
    const int a_row_l  = ((lid >> 3) & 1) * 8 + (lid & 7);
    const int a_koff_l = (lid >> 4) * 8;
    const int b_row_l  = ((lid >> 4) & 1) * 8 + (lid & 7);
    const int b_koff_l = ((lid >> 3) & 1) * 8;

    do_load(0);
    do_load(1);

    for (int ls = 0; ls < NSTG; ++ls) {
        int kc  = ls & 15;
        int nt  = ls >> 4;
        int buf = ls - (ls / 3) * 3;

        if (ls < NSTG - 1) { CP_WAIT1(); } else { CP_WAIT0(); }
        __syncthreads();

        const uint32_t Ab = sA + buf * A_TILE_B;
        const uint32_t Bb = sB + buf * B_TILE_B;

        #pragma unroll
        for (int q = 0; q < 4; q++) {
            uint32_t af[2][4];
            #pragma unroll
            for (int i = 0; i < 2; i++) {
                uint32_t addr = Ab + (mbase + i * 16 + a_row_l) * (AST * 2)
                              + (q * 16 + a_koff_l) * 2;
                LDSM_X4(af[i][0], af[i][1], af[i][2], af[i][3], addr);
            }
            #pragma unroll
            for (int j2 = 0; j2 < 4; j2++) {
                uint32_t b0, b1, b2, b3r;
                uint32_t addr = Bb + (nbase + j2 * 16 + b_row_l) * (AST * 2)
                              + (q * 16 + b_koff_l) * 2;
                LDSM_X4(b0, b1, b2, b3r, addr);
                #pragma unroll
                for (int i = 0; i < 2; i++) {
                    mma_f16(acc[i][j2 * 2],     af[i][0], af[i][1], af[i][2], af[i][3], b0, b1);
                    mma_f16(acc[i][j2 * 2 + 1], af[i][0], af[i][1], af[i][2], af[i][3], b2, b3r);
                }
            }
        }

        if (kc == 0) {
            // stage u[0..31][nt*256 .. +255] into smem (readers at kc==15)
            #pragma unroll
            for (int t = 0; t < 16; t++) {
                int idx = tid + t * NTHR;
                int n = idx >> 8, el = idx & 255;
                su[n * SU_STRIDE + el] = g_u[n * EE + nt * NTILE + el];
            }
        }

        if (kc == 15) {
            // epilogue: +u, tanh, *W3; fold into row partials; reset acc
            #pragma unroll
            for (int i = 0; i < 2; i++) {
                int r0 = mbase + i * 16 + g;
                int n0 = r0 & 31;
                int n1 = (r0 + 8) & 31;
                #pragma unroll
                for (int j = 0; j < 8; j++) {
                    int el = nbase + j * 8 + 2 * tg;
                    int e  = nt * NTILE + el;
                    float w30 = __ldg(&W3[e]);
                    float w31 = __ldg(&W3[e + 1]);
                    float z00 = acc[i][j][0] + su[n0 * SU_STRIDE + el];
                    float z01 = acc[i][j][1] + su[n0 * SU_STRIDE + el + 1];
                    float z10 = acc[i][j][2] + su[n1 * SU_STRIDE + el];
                    float z11 = acc[i][j][3] + su[n1 * SU_STRIDE + el + 1];
                    pa[i * 2]     = fmaf(tanhf(z00), w30, pa[i * 2]);
                    pa[i * 2]     = fmaf(tanhf(z01), w31, pa[i * 2]);
                    pa[i * 2 + 1] = fmaf(tanhf(z10), w30, pa[i * 2 + 1]);
                    pa[i * 2 + 1] = fmaf(tanhf(z11), w31, pa[i * 2 + 1]);
                    acc[i][j][0] = acc[i][j][1] = acc[i][j][2] = acc[i][j][3] = 0.f;
                }
            }
        }

        __syncthreads();
        if (ls + 2 < NSTG) do_load(ls + 2);
    }

    // reduce pa over 4 lanes of each group, then across the 4 n-warps
    #pragma unroll
    for (int i = 0; i < 2; i++)
        #pragma unroll
        for (int h = 0; h < 2; h++) {
            float v = pa[i * 2 + h];
            v += __shfl_xor_sync(0xffffffffu, v, 1);
            v += __shfl_xor_sync(0xffffffffu, v, 2);
            if (tg == 0) red[(mbase + i * 16 + h * 8 + g) * 4 + warp_n] = v;
        }
    __syncthreads();
    if (tid < 128) {
        int m = m0 + tid;
        float a = red[tid * 4] + red[tid * 4 + 1] + red[tid * 4 + 2] + red[tid * 4 + 3]
                + __ldg(&b3[0]);
        g_a[(m & 31) * SS + (m >> 5)] = a;
    }
}

// ============================================================================
// Kernel 3: softmax over S per column n
// ============================================================================
__global__ void k_softmax(float* __restrict__ alpha_out, int write_out) {
    int n = blockIdx.x;
    int tid = threadIdx.x;
    __shared__ float sred[256];
    const float* av = g_a + n * SS;

    float vals[8];
    float mx = -1e30f;
    #pragma unroll
    for (int i = 0; i < 8; i++) { vals[i] = av[tid + i * 256]; mx = fmaxf(mx, vals[i]); }
    sred[tid] = mx; __syncthreads();
    for (int o = 128; o; o >>= 1) { if (tid < o) sred[tid] = fmaxf(sred[tid], sred[tid + o]); __syncthreads(); }
    mx = sred[0]; __syncthreads();

    float lsum = 0.f;
    #pragma unroll
    for (int i = 0; i < 8; i++) { vals[i] = __expf(vals[i] - mx); lsum += vals[i]; }
    sred[tid] = lsum; __syncthreads();
    for (int o = 128; o; o >>= 1) { if (tid < o) sred[tid] += sred[tid + o]; __syncthreads(); }
    float inv = 1.f / sred[0];

    #pragma unroll
    for (int i = 0; i < 8; i++) {
        int s = tid + i * 256;
        float al = vals[i] * inv;
        g_alpha[n * SS + s] = al;
        if (write_out) alpha_out[s * NN + n] = al;
    }
}

// ============================================================================
// Kernel 4/5: context c[n][h] = sum_s alpha[s,n]*x[s,n,h]  (fp16 x, fp32 acc)
// ============================================================================
__global__ void k_cpart() {
    int chunk = blockIdx.x;   // 0..31
    int n     = blockIdx.y;   // 0..31
    int h0    = threadIdx.x * 4;
    float4 acc = make_float4(0.f, 0.f, 0.f, 0.f);
    int sbeg = chunk * (SS / 32);
    for (int s = sbeg; s < sbeg + (SS / 32); ++s) {
        float al = g_alpha[n * SS + s];
        uint2 raw = *(const uint2*)(g_Xh + (size_t)(s * NN + n) * HH + h0);
        __half2 hlo = *(__half2*)&raw.x;
        __half2 hhi = *(__half2*)&raw.y;
        float2 lo = __half22float2(hlo);
        float2 hi = __half22float2(hhi);
        acc.x = fmaf(al, lo.x, acc.x);
        acc.y = fmaf(al, lo.y, acc.y);
        acc.z = fmaf(al, hi.x, acc.z);
        acc.w = fmaf(al, hi.y, acc.w);
    }
    *(float4*)(g_cpart + ((size_t)(chunk * NN + n) * HH) + h0) = acc;
}

__global__ void k_cfinal(float* __restrict__ cout) {
    int idx = blockIdx.x * 256 + threadIdx.x;   // 0 .. N*H-1
    float s = 0.f;
    #pragma unroll
    for (int ch = 0; ch < 32; ++ch) s += g_cpart[(size_t)ch * NN * HH + idx];
    cout[idx] = s;
}

// ============================================================================
extern "C" void kernel_launch(void* const* d_in, const int* in_sizes, int n_in,
                              void* d_out, int out_size) {
    const float* out_e  = (const float*)d_in[0];
    const float* hidden = (const float*)d_in[1];
    const float* W1     = (const float*)d_in[2];
    const float* b1     = (const float*)d_in[3];
    const float* W2     = (const float*)d_in[4];
    const float* b2     = (const float*)d_in[5];
    const float* W3     = (const float*)d_in[6];
    const float* b3     = (const float*)d_in[7];
    float* outp = (float*)d_out;

    __half *dXh = nullptr, *dW2h = nullptr;
    cudaGetSymbolAddress((void**)&dXh,  g_Xh);
    cudaGetSymbolAddress((void**)&dW2h, g_W2h);
    k_cvt<<<((size_t)MM * HH / 4 + 255) / 256, 256>>>(out_e, dXh, MM * (HH / 4));
    k_cvt<<<(EE * HH / 4 + 255) / 256, 256>>>(W2, dW2h, EE * HH / 4);

    k_u<<<(NN * EE) / 8, 256>>>(hidden, W1, b1, b2);

    const int smem_bytes = 3 * A_TILE_B + 3 * B_TILE_B + (32 * SU_STRIDE + 128 * 4) * 4;
    static int cfg_done = 0;
    if (!cfg_done) {
        cudaFuncSetAttribute(k_gemm, cudaFuncAttributeMaxDynamicSharedMemorySize, smem_bytes);
        cfg_done = 1;
    }
    k_gemm<<<MM / 128, NTHR, smem_bytes>>>(W3, b3);

    int has_both   = (out_size >= NN * HH + SS * NN);
    int alpha_only = (!has_both && out_size == SS * NN);
    float* alpha_dst = has_both ? (outp + NN * HH) : (alpha_only ? outp : nullptr);

    k_softmax<<<NN, 256>>>(alpha_dst, alpha_dst != nullptr);

    if (!alpha_only) {
        dim3 g(32, NN);
        k_cpart<<<g, 256>>>();
        k_cfinal<<<(NN * HH) / 256, 256>>>(outp);
    }
}

// round 12
// speedup vs baseline: 1.1102x; 1.1069x over previous
#include <cuda_runtime.h>
#include <cuda_fp16.h>
#include <math.h>
#include <stdint.h>

#define SS 2048
#define NN 32
#define HH 1024
#define EE 1024
#define MM (SS*NN)   // 65536 rows

// ---- scratch (static __device__: no allocation in kernel_launch) ----
__device__ float  g_u[NN*EE];
__device__ float  g_a[NN*SS];
__device__ float  g_alpha[NN*SS];
__device__ float  g_cpart[32*NN*HH];
__device__ __half g_Xh[(size_t)MM*HH];   // fp16 copy of out_e (128MB)
__device__ __half g_W2h[(size_t)EE*HH];  // fp16 copy of W2 (2MB)

// ============================================================================
// PTX helpers (sm_80+ portable)
// ============================================================================
__device__ __forceinline__ uint32_t smem_u32(const void* p) {
    uint32_t a;
    asm("{ .reg .u64 t; cvta.to.shared.u64 t, %1; cvt.u32.u64 %0, t; }" : "=r"(a) : "l"(p));
    return a;
}
#define CP_ASYNC16(dst, src) \
    asm volatile("cp.async.cg.shared.global [%0], [%1], 16;" :: "r"(dst), "l"(src) : "memory")
#define CP_COMMIT() asm volatile("cp.async.commit_group;" ::: "memory")
#define CP_WAIT1()  asm volatile("cp.async.wait_group 1;" ::: "memory")
#define CP_WAIT0()  asm volatile("cp.async.wait_group 0;" ::: "memory")

#define LDSM_X4(r0, r1, r2, r3, addr) \
    asm volatile("ldmatrix.sync.aligned.m8n8.x4.shared.b16 {%0,%1,%2,%3}, [%4];" \
        : "=r"(r0), "=r"(r1), "=r"(r2), "=r"(r3) : "r"(addr))

__device__ __forceinline__ void mma_f16(float c[4],
                                        uint32_t a0, uint32_t a1, uint32_t a2, uint32_t a3,
                                        uint32_t b0, uint32_t b1) {
    asm volatile(
        "mma.sync.aligned.m16n8k16.row.col.f32.f16.f16.f32 "
        "{%0,%1,%2,%3}, {%4,%5,%6,%7}, {%8,%9}, {%0,%1,%2,%3};"
        : "+f"(c[0]), "+f"(c[1]), "+f"(c[2]), "+f"(c[3])
        : "r"(a0), "r"(a1), "r"(a2), "r"(a3), "r"(b0), "r"(b1));
}

// ============================================================================
// Kernel 0a: zero the logit accumulator
// ============================================================================
__global__ void k_zero() {
    g_a[blockIdx.x * 256 + threadIdx.x] = 0.f;
}

// ============================================================================
// Kernel 0b: fp32 -> fp16 conversion
// ============================================================================
__global__ void k_cvt(const float* __restrict__ src, __half* __restrict__ dst, int n4) {
    int i = blockIdx.x * blockDim.x + threadIdx.x;
    if (i >= n4) return;
    float4 v = ((const float4*)src)[i];
    __half2 lo = __floats2half2_rn(v.x, v.y);
    __half2 hi = __floats2half2_rn(v.z, v.w);
    uint2 w;
    w.x = *(uint32_t*)&lo;
    w.y = *(uint32_t*)&hi;
    ((uint2*)dst)[i] = w;
}

// ============================================================================
// Kernel 1: u[n][e] = hidden_d[n]·W1[e] + b1[e] + b2[e]
// ============================================================================
__global__ void k_u(const float* __restrict__ hidden, const float* __restrict__ W1,
                    const float* __restrict__ b1, const float* __restrict__ b2) {
    int gw = (blockIdx.x * blockDim.x + threadIdx.x) >> 5;
    int lane = threadIdx.x & 31;
    if (gw >= NN * EE) return;
    int n = gw >> 10;
    int e = gw & (EE - 1);
    const float* hv = hidden + n * HH;
    const float* wv = W1 + (size_t)e * HH;
    float s = 0.f;
    #pragma unroll 4
    for (int h = lane; h < HH; h += 32) s = fmaf(hv[h], wv[h], s);
    #pragma unroll
    for (int o = 16; o; o >>= 1) s += __shfl_down_sync(0xffffffffu, s, o);
    if (lane == 0) g_u[n * EE + e] = s + b1[e] + b2[e];
}

// ============================================================================
// Kernel 2: fp16 mma.sync fused  X·W2ᵀ -> +u -> tanh -> ·W3 reduce -> a[m]
//   CTA: 128 rows x 512 e-cols (2 n-tiles of 256). grid = 1024 (2 CTAs per
//   row-block; partial logits combined via one deterministic atomicAdd).
//   512 threads = 16 warps, warp tile 32x64 (4m x 4n), 3-stage cp.async.
// ============================================================================
#define NSTG 32           // 2 n-tiles * 16 k-chunks
#define AST 72            // smem stride (halfs)
#define A_TILE_B (128*AST*2)   // 18432 B
#define B_TILE_B (256*AST*2)   // 36864 B
#define NTILE 256
#define SU_STRIDE 264     // 256 + 8 pad (floats)
#define NTHR 512

__global__ void __launch_bounds__(NTHR, 1)
k_gemm(const float* __restrict__ W3) {
    extern __shared__ char smraw[];
    __half* As = (__half*)smraw;                                  // 3 * 18432 B
    __half* Bs = (__half*)(smraw + 3 * A_TILE_B);                 // 3 * 36864 B
    float*  su = (float*)(smraw + 3 * A_TILE_B + 3 * B_TILE_B);   // 32*264*4 B
    float* red = su + 32 * SU_STRIDE;                             // 128*4 floats

    const int tid = threadIdx.x;
    const int wid = tid >> 5;
    const int lid = tid & 31;
    const int g   = lid >> 2;
    const int tg  = lid & 3;
    const int warp_m = wid & 3;        // 4 m-warps of 32 rows
    const int warp_n = wid >> 2;       // 4 n-warps of 64 cols
    const int mbase = warp_m * 32;
    const int nbase = warp_n * 64;
    const int rb    = blockIdx.x >> 1;      // row block
    const int eh    = blockIdx.x & 1;       // e half
    const int m0    = rb * 128;
    const int ebase = eh * 512;

    const uint32_t sA = smem_u32(As);
    const uint32_t sB = smem_u32(Bs);

    const int l_ch  = tid & 7;         // 16B chunk within 128B row
    const int l_row = tid >> 3;        // 0..63

    const __half* Xh  = g_Xh;
    const __half* W2h = g_W2h;

    auto do_load = [&](int ls) {
        int nt  = ls >> 4;
        int kc  = ls & 15;
        int buf = ls - (ls / 3) * 3;
        const __half* gA = Xh  + (size_t)(m0 + l_row) * HH + kc * 64 + l_ch * 8;
        uint32_t dA = sA + buf * A_TILE_B + l_row * (AST * 2) + l_ch * 16;
        #pragma unroll
        for (int t = 0; t < 2; t++) {
            CP_ASYNC16(dA, gA);
            gA += 64 * HH;
            dA += 64 * AST * 2;
        }
        const __half* gB = W2h + (size_t)(ebase + nt * NTILE + l_row) * HH + kc * 64 + l_ch * 8;
        uint32_t dB = sB + buf * B_TILE_B + l_row * (AST * 2) + l_ch * 16;
        #pragma unroll
        for (int t = 0; t < 4; t++) {
            CP_ASYNC16(dB, gB);
            gB += 64 * HH;
            dB += 64 * AST * 2;
        }
        CP_COMMIT();
    };

    float acc[2][8][4];
    #pragma unroll
    for (int i = 0; i < 2; i++)
        #pragma unroll
        for (int j = 0; j < 8; j++)
            #pragma unroll
            for (int q = 0; q < 4; q++) acc[i][j][q] = 0.f;
    float pa[4] = {0.f, 0.f, 0.f, 0.f};

    // ldmatrix lane-address components
    const int a_row_l  = ((lid >> 3) & 1) * 8 + (lid & 7);
    const int a_koff_l = (lid >> 4) * 8;
    const int b_row_l  = ((lid >> 4) & 1) * 8 + (lid & 7);
    const int b_koff_l = ((lid >> 3) & 1) * 8;

    do_load(0);
    do_load(1);

    for (int ls = 0; ls < NSTG; ++ls) {
        int kc  = ls & 15;
        int nt  = ls >> 4;
        int buf = ls - (ls / 3) * 3;

        if (ls < NSTG - 1) { CP_WAIT1(); } else { CP_WAIT0(); }
        __syncthreads();

        const uint32_t Ab = sA + buf * A_TILE_B;
        const uint32_t Bb = sB + buf * B_TILE_B;

        #pragma unroll
        for (int q = 0; q < 4; q++) {
            uint32_t af[2][4];
            #pragma unroll
            for (int i = 0; i < 2; i++) {
                uint32_t addr = Ab + (mbase + i * 16 + a_row_l) * (AST * 2)
                              + (q * 16 + a_koff_l) * 2;
                LDSM_X4(af[i][0], af[i][1], af[i][2], af[i][3], addr);
            }
            #pragma unroll
            for (int j2 = 0; j2 < 4; j2++) {
                uint32_t b0, b1, b2, b3r;
                uint32_t addr = Bb + (nbase + j2 * 16 + b_row_l) * (AST * 2)
                              + (q * 16 + b_koff_l) * 2;
                LDSM_X4(b0, b1, b2, b3r, addr);
                #pragma unroll
                for (int i = 0; i < 2; i++) {
                    mma_f16(acc[i][j2 * 2],     af[i][0], af[i][1], af[i][2], af[i][3], b0, b1);
                    mma_f16(acc[i][j2 * 2 + 1], af[i][0], af[i][1], af[i][2], af[i][3], b2, b3r);
                }
            }
        }

        if (kc == 0) {
            // stage u[0..31][ebase + nt*256 .. +255] into smem (readers at kc==15)
            #pragma unroll
            for (int t = 0; t < 16; t++) {
                int idx = tid + t * NTHR;
                int n = idx >> 8, el = idx & 255;
                su[n * SU_STRIDE + el] = g_u[n * EE + ebase + nt * NTILE + el];
            }
        }

        if (kc == 15) {
            // epilogue: +u, tanh, *W3; fold into row partials; reset acc
            #pragma unroll
            for (int i = 0; i < 2; i++) {
                int r0 = mbase + i * 16 + g;
                int n0 = r0 & 31;
                int n1 = (r0 + 8) & 31;
                #pragma unroll
                for (int j = 0; j < 8; j++) {
                    int el = nbase + j * 8 + 2 * tg;
                    int e  = ebase + nt * NTILE + el;
                    float w30 = __ldg(&W3[e]);
                    float w31 = __ldg(&W3[e + 1]);
                    float z00 = acc[i][j][0] + su[n0 * SU_STRIDE + el];
                    float z01 = acc[i][j][1] + su[n0 * SU_STRIDE + el + 1];
                    float z10 = acc[i][j][2] + su[n1 * SU_STRIDE + el];
                    float z11 = acc[i][j][3] + su[n1 * SU_STRIDE + el + 1];
                    pa[i * 2]     = fmaf(tanhf(z00), w30, pa[i * 2]);
                    pa[i * 2]     = fmaf(tanhf(z01), w31, pa[i * 2]);
                    pa[i * 2 + 1] = fmaf(tanhf(z10), w30, pa[i * 2 + 1]);
                    pa[i * 2 + 1] = fmaf(tanhf(z11), w31, pa[i * 2 + 1]);
                    acc[i][j][0] = acc[i][j][1] = acc[i][j][2] = acc[i][j][3] = 0.f;
                }
            }
        }

        __syncthreads();
        if (ls + 2 < NSTG) do_load(ls + 2);
    }

    // reduce pa over 4 lanes of each group, then across the 4 n-warps
    #pragma unroll
    for (int i = 0; i < 2; i++)
        #pragma unroll
        for (int h = 0; h < 2; h++) {
            float v = pa[i * 2 + h];
            v += __shfl_xor_sync(0xffffffffu, v, 1);
            v += __shfl_xor_sync(0xffffffffu, v, 2);
            if (tg == 0) red[(mbase + i * 16 + h * 8 + g) * 4 + warp_n] = v;
        }
    __syncthreads();
    if (tid < 128) {
        int m = m0 + tid;
        float a = red[tid * 4] + red[tid * 4 + 1] + red[tid * 4 + 2] + red[tid * 4 + 3];
        // two CTAs contribute per logit; fp add is commutative -> deterministic
        atomicAdd(&g_a[(m & 31) * SS + (m >> 5)], a);
    }
}

// ============================================================================
// Kernel 3: softmax over S per column n  (b3 omitted: softmax shift-invariant)
// ============================================================================
__global__ void k_softmax(float* __restrict__ alpha_out, int write_out) {
    int n = blockIdx.x;
    int tid = threadIdx.x;
    __shared__ float sred[256];
    const float* av = g_a + n * SS;

    float vals[8];
    float mx = -1e30f;
    #pragma unroll
    for (int i = 0; i < 8; i++) { vals[i] = av[tid + i * 256]; mx = fmaxf(mx, vals[i]); }
    sred[tid] = mx; __syncthreads();
    for (int o = 128; o; o >>= 1) { if (tid < o) sred[tid] = fmaxf(sred[tid], sred[tid + o]); __syncthreads(); }
    mx = sred[0]; __syncthreads();

    float lsum = 0.f;
    #pragma unroll
    for (int i = 0; i < 8; i++) { vals[i] = __expf(vals[i] - mx); lsum += vals[i]; }
    sred[tid] = lsum; __syncthreads();
    for (int o = 128; o; o >>= 1) { if (tid < o) sred[tid] += sred[tid + o]; __syncthreads(); }
    float inv = 1.f / sred[0];

    #pragma unroll
    for (int i = 0; i < 8; i++) {
        int s = tid + i * 256;
        float al = vals[i] * inv;
        g_alpha[n * SS + s] = al;
        if (write_out) alpha_out[s * NN + n] = al;
    }
}

// ============================================================================
// Kernel 4/5: context c[n][h] = sum_s alpha[s,n]*x[s,n,h]  (fp16 x, fp32 acc)
// ============================================================================
__global__ void k_cpart() {
    int chunk = blockIdx.x;   // 0..31
    int n     = blockIdx.y;   // 0..31
    int h0    = threadIdx.x * 4;
    float4 acc = make_float4(0.f, 0.f, 0.f, 0.f);
    int sbeg = chunk * (SS / 32);
    for (int s = sbeg; s < sbeg + (SS / 32); ++s) {
        float al = g_alpha[n * SS + s];
        uint2 raw = *(const uint2*)(g_Xh + (size_t)(s * NN + n) * HH + h0);
        __half2 hlo = *(__half2*)&raw.x;
        __half2 hhi = *(__half2*)&raw.y;
        float2 lo = __half22float2(hlo);
        float2 hi = __half22float2(hhi);
        acc.x = fmaf(al, lo.x, acc.x);
        acc.y = fmaf(al, lo.y, acc.y);
        acc.z = fmaf(al, hi.x, acc.z);
        acc.w = fmaf(al, hi.y, acc.w);
    }
    *(float4*)(g_cpart + ((size_t)(chunk * NN + n) * HH) + h0) = acc;
}

__global__ void k_cfinal(float* __restrict__ cout) {
    int idx = blockIdx.x * 256 + threadIdx.x;   // 0 .. N*H-1
    float s = 0.f;
    #pragma unroll
    for (int ch = 0; ch < 32; ++ch) s += g_cpart[(size_t)ch * NN * HH + idx];
    cout[idx] = s;
}

// ============================================================================
extern "C" void kernel_launch(void* const* d_in, const int* in_sizes, int n_in,
                              void* d_out, int out_size) {
    const float* out_e  = (const float*)d_in[0];
    const float* hidden = (const float*)d_in[1];
    const float* W1     = (const float*)d_in[2];
    const float* b1     = (const float*)d_in[3];
    const float* W2     = (const float*)d_in[4];
    const float* b2     = (const float*)d_in[5];
    const float* W3     = (const float*)d_in[6];
    float* outp = (float*)d_out;

    __half *dXh = nullptr, *dW2h = nullptr;
    cudaGetSymbolAddress((void**)&dXh,  g_Xh);
    cudaGetSymbolAddress((void**)&dW2h, g_W2h);

    k_zero<<<NN * SS / 256, 256>>>();
    k_cvt<<<((size_t)MM * HH / 4 + 255) / 256, 256>>>(out_e, dXh, MM * (HH / 4));
    k_cvt<<<(EE * HH / 4 + 255) / 256, 256>>>(W2, dW2h, EE * HH / 4);

    k_u<<<(NN * EE) / 8, 256>>>(hidden, W1, b1, b2);

    const int smem_bytes = 3 * A_TILE_B + 3 * B_TILE_B + (32 * SU_STRIDE + 128 * 4) * 4;
    static int cfg_done = 0;
    if (!cfg_done) {
        cudaFuncSetAttribute(k_gemm, cudaFuncAttributeMaxDynamicSharedMemorySize, smem_bytes);
        cfg_done = 1;
    }
    k_gemm<<<(MM / 128) * 2, NTHR, smem_bytes>>>(W3);

    int has_both   = (out_size >= NN * HH + SS * NN);
    int alpha_only = (!has_both && out_size == SS * NN);
    float* alpha_dst = has_both ? (outp + NN * HH) : (alpha_only ? outp : nullptr);

    k_softmax<<<NN, 256>>>(alpha_dst, alpha_dst != nullptr);

    if (!alpha_only) {
        dim3 g(32, NN);
        k_cpart<<<g, 256>>>();
        k_cfinal<<<(NN * HH) / 256, 256>>>(outp);
    }
}